// round 2
// baseline (speedup 1.0000x reference)
#include <cuda_runtime.h>
#include <math.h>

// Problem dims (fixed by setup_inputs)
#define B_ 1024
#define F_ 4096
#define V_ 20000
#define E_ 512
#define H_ 1024
#define L_ 20
#define D_ 4

// ---------------- scratch (device globals; no allocation allowed) ----------
__device__ float g_h[B_ * H_];
__device__ float g_c[B_ * H_];
__device__ float g_hr[B_ * H_];
__device__ float g_cr[B_ * H_];
__device__ float g_x[B_ * E_];
__device__ float g_gates[B_ * 4 * H_];
__device__ float g_logits[(size_t)B_ * V_];
__device__ int   g_msg[L_ * B_];
__device__ float g_lp[B_];
__device__ float g_r[B_ * F_];
__device__ float g_ts[B_ * B_];
__device__ float g_ds[D_ * B_ * B_];

// ---------------- SGEMM: C[M,N] = A[M,K] @ B[N,K]^T (+bias[n]) (+=C) -------
// 128x128 block tile, K-tile 8, double-buffered, 256 threads, 8x8 per thread.
// M must be a multiple of 128 (true for all call sites); N may be ragged.
__global__ __launch_bounds__(256, 2)
void sgemm_nt(const float* __restrict__ A, const float* __restrict__ Bm,
              float* __restrict__ C, const float* __restrict__ bias,
              int M, int N, int K, int accum)
{
    __shared__ float As[2][8][128];
    __shared__ float Bs[2][8][128];
    const int t  = threadIdx.x;
    const int m0 = blockIdx.y << 7;
    const int n0 = blockIdx.x << 7;
    const int tx = t & 15;
    const int ty = t >> 4;
    const int lr = t & 127;          // tile row this thread loads
    const int lk = (t >> 7) << 2;    // k offset (0 or 4)

    const float* Ap = A + (size_t)(m0 + lr) * K + lk;
    const int brow  = n0 + lr;
    const float* Bp = Bm + (size_t)brow * K + lk;
    const bool bok  = brow < N;

    float acc[8][8];
#pragma unroll
    for (int i = 0; i < 8; ++i)
#pragma unroll
        for (int j = 0; j < 8; ++j) acc[i][j] = 0.f;

    const int KT = K >> 3;

    float4 ra = *(const float4*)Ap;
    float4 rb = bok ? *(const float4*)Bp : make_float4(0.f, 0.f, 0.f, 0.f);
    As[0][lk + 0][lr] = ra.x; As[0][lk + 1][lr] = ra.y;
    As[0][lk + 2][lr] = ra.z; As[0][lk + 3][lr] = ra.w;
    Bs[0][lk + 0][lr] = rb.x; Bs[0][lk + 1][lr] = rb.y;
    Bs[0][lk + 2][lr] = rb.z; Bs[0][lk + 3][lr] = rb.w;
    __syncthreads();

    int buf = 0;
    for (int kt = 0; kt < KT; ++kt) {
        if (kt + 1 < KT) {
            ra = *(const float4*)(Ap + (kt + 1) * 8);
            rb = bok ? *(const float4*)(Bp + (kt + 1) * 8)
                     : make_float4(0.f, 0.f, 0.f, 0.f);
        }
#pragma unroll
        for (int kk = 0; kk < 8; ++kk) {
            float4 a0 = *(const float4*)&As[buf][kk][ty << 2];
            float4 a1 = *(const float4*)&As[buf][kk][64 + (ty << 2)];
            float4 b0 = *(const float4*)&Bs[buf][kk][tx << 2];
            float4 b1 = *(const float4*)&Bs[buf][kk][64 + (tx << 2)];
            float av[8] = {a0.x, a0.y, a0.z, a0.w, a1.x, a1.y, a1.z, a1.w};
            float bv[8] = {b0.x, b0.y, b0.z, b0.w, b1.x, b1.y, b1.z, b1.w};
#pragma unroll
            for (int i = 0; i < 8; ++i)
#pragma unroll
                for (int j = 0; j < 8; ++j)
                    acc[i][j] = fmaf(av[i], bv[j], acc[i][j]);
        }
        if (kt + 1 < KT) {
            const int nb = buf ^ 1;
            As[nb][lk + 0][lr] = ra.x; As[nb][lk + 1][lr] = ra.y;
            As[nb][lk + 2][lr] = ra.z; As[nb][lk + 3][lr] = ra.w;
            Bs[nb][lk + 0][lr] = rb.x; Bs[nb][lk + 1][lr] = rb.y;
            Bs[nb][lk + 2][lr] = rb.z; Bs[nb][lk + 3][lr] = rb.w;
            __syncthreads();
            buf = nb;
        }
    }

#pragma unroll
    for (int i = 0; i < 8; ++i) {
        const int mm = m0 + (i & 3) + (ty << 2) + ((i >> 2) << 6);
        const size_t rowoff = (size_t)mm * N;
#pragma unroll
        for (int j = 0; j < 8; ++j) {
            const int nn = n0 + (j & 3) + (tx << 2) + ((j >> 2) << 6);
            if (nn < N) {
                float v = acc[i][j];
                if (bias)  v += bias[nn];
                if (accum) v += C[rowoff + nn];
                C[rowoff + nn] = v;
            }
        }
    }
}

// ---------------- LSTM pointwise: gate order i,f,g,o -----------------------
__global__ void lstm_update(const float* __restrict__ gates,
                            float* __restrict__ h, float* __restrict__ c,
                            int firstStep)
{
    const int idx = blockIdx.x * blockDim.x + threadIdx.x;   // over B*H
    const int b = idx >> 10;
    const int j = idx & 1023;
    const float* g = gates + (size_t)b * (4 * H_);
    const float gi = g[j];
    const float gf = g[H_ + j];
    const float gg = g[2 * H_ + j];
    const float go = g[3 * H_ + j];
    const float si = 1.f / (1.f + expf(-gi));
    const float sf = 1.f / (1.f + expf(-gf));
    const float so = 1.f / (1.f + expf(-go));
    const float cprev = firstStep ? 0.f : c[idx];
    const float cn = sf * cprev + si * tanhf(gg);
    c[idx] = cn;
    h[idx] = so * tanhf(cn);
}

// ---------------- per-row argmax (+ last-step logsumexp) -------------------
// Matches jnp.argmax semantics: first occurrence wins on ties.
__global__ void argmax_lse(const float* __restrict__ logits,
                           int* __restrict__ msg_t,
                           float* __restrict__ lp, int computeLp)
{
    __shared__ float sv[256];
    __shared__ int   si[256];
    const int b = blockIdx.x;
    const int tid = threadIdx.x;
    const float* row = logits + (size_t)b * V_;

    float best = -INFINITY;
    int bidx = 0x7fffffff;
    for (int i = tid; i < V_; i += 256) {
        const float v = row[i];
        if (v > best) { best = v; bidx = i; }   // strided i ascending -> first-max kept
    }
    sv[tid] = best; si[tid] = bidx;
    __syncthreads();
    for (int s = 128; s > 0; s >>= 1) {
        if (tid < s) {
            const float v2 = sv[tid + s];
            const int   i2 = si[tid + s];
            if (v2 > sv[tid] || (v2 == sv[tid] && i2 < si[tid])) {
                sv[tid] = v2; si[tid] = i2;
            }
        }
        __syncthreads();
    }
    const float m = sv[0];
    if (tid == 0) msg_t[b] = si[0];

    if (computeLp) {
        float s = 0.f;
        for (int i = tid; i < V_; i += 256) s += expf(row[i] - m);
        __syncthreads();
        sv[tid] = s;
        __syncthreads();
        for (int st = 128; st > 0; st >>= 1) {
            if (tid < st) sv[tid] += sv[tid + st];
            __syncthreads();
        }
        // argmax value == max, so logp at argmax = -log(sum exp(l - max))
        if (tid == 0) lp[b] = -logf(sv[0]);
    }
}

// ---------------- embedding gather -----------------------------------------
__global__ void gather_emb(const float* __restrict__ emb,
                           const int* __restrict__ idx,
                           const int* __restrict__ scalar_idx,
                           float* __restrict__ out, int E)
{
    const int b = blockIdx.x;
    const int id = idx ? idx[b] : *scalar_idx;
    const float* src = emb + (size_t)id * E;
    float* dst = out + (size_t)b * E;
    for (int i = threadIdx.x; i < E; i += blockDim.x) dst[i] = src[i];
}

// ---------------- final hinge loss + accuracy -------------------------------
__device__ __forceinline__ float blockReduceSum(float v, float* sbuf)
{
    const int tid = threadIdx.x;
    sbuf[tid] = v;
    __syncthreads();
    for (int s = 128; s > 0; s >>= 1) {
        if (tid < s) sbuf[tid] += sbuf[tid + s];
        __syncthreads();
    }
    const float r = sbuf[0];
    __syncthreads();
    return r;
}

__global__ void zero_out(float* out)
{
    if (threadIdx.x < 2) out[threadIdx.x] = 0.f;
}

__global__ void final_reduce(const float* __restrict__ ts,
                             const float* __restrict__ ds,
                             const float* __restrict__ lp,
                             float* __restrict__ out)
{
    __shared__ float sbuf[256];
    const int j = blockIdx.x;
    float S = 0.f, tp = 0.f;
    float dp[4] = {0.f, 0.f, 0.f, 0.f};
    for (int k = threadIdx.x; k < B_; k += 256) {
        const float t = ts[(size_t)j * B_ + k];
        const float l = lp[k];
        float hsum = 0.f;
#pragma unroll
        for (int d = 0; d < D_; ++d) {
            const float dv = ds[((size_t)d * B_ + j) * B_ + k];
            hsum += fmaxf(0.f, 1.f - t + dv);
            dp[d] += expf(dv);
        }
        S += hsum * l;
        tp += expf(t);
    }
    S  = blockReduceSum(S, sbuf);
    tp = blockReduceSum(tp, sbuf);
    float dpr[4];
#pragma unroll
    for (int d = 0; d < D_; ++d) dpr[d] = blockReduceSum(dp[d], sbuf);
    if (threadIdx.x == 0) {
        atomicAdd(&out[0], -S * (1.f / ((float)B_ * (float)B_)));
        const int win = (tp >= dpr[0]) && (tp >= dpr[1]) &&
                        (tp >= dpr[2]) && (tp >= dpr[3]);
        atomicAdd(&out[1], win ? (1.f / (float)B_) : 0.f);
    }
}

// ---------------- host side --------------------------------------------------
static inline void gemm(const float* A, const float* Bm, float* C,
                        const float* bias, int M, int N, int K, int accum)
{
    dim3 grid((N + 127) / 128, M / 128);
    sgemm_nt<<<grid, 256>>>(A, Bm, C, bias, M, N, K, accum);
}

extern "C" void kernel_launch(void* const* d_in, const int* in_sizes, int n_in,
                              void* d_out, int out_size)
{
    (void)in_sizes; (void)n_in; (void)out_size;

    const float* target   = (const float*)d_in[0];
    const float* distract = (const float*)d_in[1];
    const int*   start    = (const int*)d_in[2];
    /* d_in[3] = max_sentence_length (compile-time L_=20) */
    const float* emb_s  = (const float*)d_in[4];
    const float* Wih_s  = (const float*)d_in[5];
    const float* Whh_s  = (const float*)d_in[6];
    const float* bih_s  = (const float*)d_in[7];
    const float* bhh_s  = (const float*)d_in[8];
    const float* affsW  = (const float*)d_in[9];
    const float* affsb  = (const float*)d_in[10];
    const float* probsW = (const float*)d_in[11];
    const float* probsb = (const float*)d_in[12];
    const float* emb_r  = (const float*)d_in[13];
    const float* Wih_r  = (const float*)d_in[14];
    const float* Whh_r  = (const float*)d_in[15];
    const float* bih_r  = (const float*)d_in[16];
    const float* bhh_r  = (const float*)d_in[17];
    const float* affrW  = (const float*)d_in[18];
    const float* affrb  = (const float*)d_in[19];
    float* out = (float*)d_out;

    float *h, *c, *hr, *cr, *x, *gates, *logits, *r, *ts, *ds, *lp;
    int* msg;
    cudaGetSymbolAddress((void**)&h,      g_h);
    cudaGetSymbolAddress((void**)&c,      g_c);
    cudaGetSymbolAddress((void**)&hr,     g_hr);
    cudaGetSymbolAddress((void**)&cr,     g_cr);
    cudaGetSymbolAddress((void**)&x,      g_x);
    cudaGetSymbolAddress((void**)&gates,  g_gates);
    cudaGetSymbolAddress((void**)&logits, g_logits);
    cudaGetSymbolAddress((void**)&r,      g_r);
    cudaGetSymbolAddress((void**)&ts,     g_ts);
    cudaGetSymbolAddress((void**)&ds,     g_ds);
    cudaGetSymbolAddress((void**)&lp,     g_lp);
    cudaGetSymbolAddress((void**)&msg,    g_msg);

    zero_out<<<1, 32>>>(out);

    // h0 = target @ aff_s_W^T + aff_s_b    [B,H], K=F
    gemm(target, affsW, h, affsb, B_, H_, F_, 0);
    // w0 = emb_s[start_token_idx] broadcast
    gather_emb<<<B_, 128>>>(emb_s, nullptr, start, x, E_);

    // ---- Sender loop ----
    for (int t = 0; t < L_; ++t) {
        gemm(x, Wih_s, gates, bih_s, B_, 4 * H_, E_, 0);
        gemm(h, Whh_s, gates, bhh_s, B_, 4 * H_, H_, 1);
        lstm_update<<<(B_ * H_) / 256, 256>>>(gates, h, c, t == 0);
        gemm(h, probsW, logits, probsb, B_, V_, H_, 0);
        argmax_lse<<<B_, 256>>>(logits, msg + t * B_, lp, t == L_ - 1);
        if (t < L_ - 1)
            gather_emb<<<B_, 128>>>(emb_s, msg + t * B_, nullptr, x, E_);
    }

    // ---- Receiver loop ----
    for (int t = 0; t < L_; ++t) {
        gather_emb<<<B_, 128>>>(emb_r, msg + t * B_, nullptr, x, E_);
        gemm(x, Wih_r, gates, bih_r, B_, 4 * H_, E_, 0);
        gemm(hr, Whh_r, gates, bhh_r, B_, 4 * H_, H_, 1);
        lstm_update<<<(B_ * H_) / 256, 256>>>(gates, hr, cr, t == 0);
    }

    // r = hr @ aff_r_W^T + aff_r_b    [B,F], K=H
    gemm(hr, affrW, r, affrb, B_, F_, H_, 0);

    // ts = target @ r^T  [B,B];  ds[d] = distractors[d] @ r^T  [D,B,B]
    gemm(target,   r, ts, nullptr, B_,      B_, F_, 0);
    gemm(distract, r, ds, nullptr, D_ * B_, B_, F_, 0);

    final_reduce<<<B_, 256>>>(ts, ds, lp, out);
}

// round 5
// speedup vs baseline: 1.0014x; 1.0014x over previous
#include <cuda_runtime.h>
#include <math.h>

// Problem dims (fixed by setup_inputs)
#define B_ 1024
#define F_ 4096
#define V_ 20000
#define E_ 512
#define H_ 1024
#define L_ 20
#define D_ 4

// ---------------- scratch (device globals; no allocation allowed) ----------
__device__ float g_h[B_ * H_];
__device__ float g_c[B_ * H_];
__device__ float g_hr[B_ * H_];
__device__ float g_cr[B_ * H_];
__device__ float g_x[B_ * E_];
__device__ float g_gates[B_ * 4 * H_];
__device__ float g_logits[(size_t)B_ * V_];
__device__ int   g_msg[L_ * B_];
__device__ float g_lp[B_];
__device__ float g_r[B_ * F_];
__device__ float g_ts[B_ * B_];
__device__ float g_ds[D_ * B_ * B_];

// ---------------- SGEMM: C[M,N] = A[M,K] @ B[N,K]^T (+bias[n]) (+=C) -------
// 128x128 block tile, K-tile 8, double-buffered, 256 threads, 8x8 per thread.
// M must be a multiple of 128 (true for all call sites); N may be ragged.
__global__ __launch_bounds__(256, 2)
void sgemm_nt(const float* __restrict__ A, const float* __restrict__ Bm,
              float* __restrict__ C, const float* __restrict__ bias,
              int M, int N, int K, int accum)
{
    __shared__ float As[2][8][128];
    __shared__ float Bs[2][8][128];
    const int t  = threadIdx.x;
    const int m0 = blockIdx.y << 7;
    const int n0 = blockIdx.x << 7;
    const int tx = t & 15;
    const int ty = t >> 4;
    const int lr = t & 127;          // tile row this thread loads
    const int lk = (t >> 7) << 2;    // k offset (0 or 4)

    const float* Ap = A + (size_t)(m0 + lr) * K + lk;
    const int brow  = n0 + lr;
    const float* Bp = Bm + (size_t)brow * K + lk;
    const bool bok  = brow < N;

    float acc[8][8];
#pragma unroll
    for (int i = 0; i < 8; ++i)
#pragma unroll
        for (int j = 0; j < 8; ++j) acc[i][j] = 0.f;

    const int KT = K >> 3;

    float4 ra = *(const float4*)Ap;
    float4 rb = bok ? *(const float4*)Bp : make_float4(0.f, 0.f, 0.f, 0.f);
    As[0][lk + 0][lr] = ra.x; As[0][lk + 1][lr] = ra.y;
    As[0][lk + 2][lr] = ra.z; As[0][lk + 3][lr] = ra.w;
    Bs[0][lk + 0][lr] = rb.x; Bs[0][lk + 1][lr] = rb.y;
    Bs[0][lk + 2][lr] = rb.z; Bs[0][lk + 3][lr] = rb.w;
    __syncthreads();

    int buf = 0;
    for (int kt = 0; kt < KT; ++kt) {
        if (kt + 1 < KT) {
            ra = *(const float4*)(Ap + (kt + 1) * 8);
            rb = bok ? *(const float4*)(Bp + (kt + 1) * 8)
                     : make_float4(0.f, 0.f, 0.f, 0.f);
        }
#pragma unroll
        for (int kk = 0; kk < 8; ++kk) {
            float4 a0 = *(const float4*)&As[buf][kk][ty << 2];
            float4 a1 = *(const float4*)&As[buf][kk][64 + (ty << 2)];
            float4 b0 = *(const float4*)&Bs[buf][kk][tx << 2];
            float4 b1 = *(const float4*)&Bs[buf][kk][64 + (tx << 2)];
            float av[8] = {a0.x, a0.y, a0.z, a0.w, a1.x, a1.y, a1.z, a1.w};
            float bv[8] = {b0.x, b0.y, b0.z, b0.w, b1.x, b1.y, b1.z, b1.w};
#pragma unroll
            for (int i = 0; i < 8; ++i)
#pragma unroll
                for (int j = 0; j < 8; ++j)
                    acc[i][j] = fmaf(av[i], bv[j], acc[i][j]);
        }
        if (kt + 1 < KT) {
            const int nb = buf ^ 1;
            As[nb][lk + 0][lr] = ra.x; As[nb][lk + 1][lr] = ra.y;
            As[nb][lk + 2][lr] = ra.z; As[nb][lk + 3][lr] = ra.w;
            Bs[nb][lk + 0][lr] = rb.x; Bs[nb][lk + 1][lr] = rb.y;
            Bs[nb][lk + 2][lr] = rb.z; Bs[nb][lk + 3][lr] = rb.w;
            __syncthreads();
            buf = nb;
        }
    }

#pragma unroll
    for (int i = 0; i < 8; ++i) {
        const int mm = m0 + (i & 3) + (ty << 2) + ((i >> 2) << 6);
        const size_t rowoff = (size_t)mm * N;
#pragma unroll
        for (int j = 0; j < 8; ++j) {
            const int nn = n0 + (j & 3) + (tx << 2) + ((j >> 2) << 6);
            if (nn < N) {
                float v = acc[i][j];
                if (bias)  v += bias[nn];
                if (accum) v += C[rowoff + nn];
                C[rowoff + nn] = v;
            }
        }
    }
}

// ---------------- LSTM pointwise: gate order i,f,g,o -----------------------
__global__ void lstm_update(const float* __restrict__ gates,
                            float* __restrict__ h, float* __restrict__ c,
                            int firstStep)
{
    const int idx = blockIdx.x * blockDim.x + threadIdx.x;   // over B*H
    const int b = idx >> 10;
    const int j = idx & 1023;
    const float* g = gates + (size_t)b * (4 * H_);
    const float gi = g[j];
    const float gf = g[H_ + j];
    const float gg = g[2 * H_ + j];
    const float go = g[3 * H_ + j];
    const float si = 1.f / (1.f + expf(-gi));
    const float sf = 1.f / (1.f + expf(-gf));
    const float so = 1.f / (1.f + expf(-go));
    const float cprev = firstStep ? 0.f : c[idx];
    const float cn = sf * cprev + si * tanhf(gg);
    c[idx] = cn;
    h[idx] = so * tanhf(cn);
}

// ---------------- per-row argmax (+ last-step logsumexp) -------------------
// Matches jnp.argmax semantics: first occurrence wins on ties.
__global__ void argmax_lse(const float* __restrict__ logits,
                           int* __restrict__ msg_t,
                           float* __restrict__ lp, int computeLp)
{
    __shared__ float sv[256];
    __shared__ int   si[256];
    const int b = blockIdx.x;
    const int tid = threadIdx.x;
    const float* row = logits + (size_t)b * V_;

    float best = -INFINITY;
    int bidx = 0x7fffffff;
    for (int i = tid; i < V_; i += 256) {
        const float v = row[i];
        if (v > best) { best = v; bidx = i; }   // strided i ascending -> first-max kept
    }
    sv[tid] = best; si[tid] = bidx;
    __syncthreads();
    for (int s = 128; s > 0; s >>= 1) {
        if (tid < s) {
            const float v2 = sv[tid + s];
            const int   i2 = si[tid + s];
            if (v2 > sv[tid] || (v2 == sv[tid] && i2 < si[tid])) {
                sv[tid] = v2; si[tid] = i2;
            }
        }
        __syncthreads();
    }
    const float m = sv[0];
    if (tid == 0) msg_t[b] = si[0];

    if (computeLp) {
        float s = 0.f;
        for (int i = tid; i < V_; i += 256) s += expf(row[i] - m);
        __syncthreads();
        sv[tid] = s;
        __syncthreads();
        for (int st = 128; st > 0; st >>= 1) {
            if (tid < st) sv[tid] += sv[tid + st];
            __syncthreads();
        }
        // argmax value == max, so logp at argmax = -log(sum exp(l - max))
        if (tid == 0) lp[b] = -logf(sv[0]);
    }
}

// ---------------- embedding gather -----------------------------------------
__global__ void gather_emb(const float* __restrict__ emb,
                           const int* __restrict__ idx,
                           const int* __restrict__ scalar_idx,
                           float* __restrict__ out, int E)
{
    const int b = blockIdx.x;
    const int id = idx ? idx[b] : *scalar_idx;
    const float* src = emb + (size_t)id * E;
    float* dst = out + (size_t)b * E;
    for (int i = threadIdx.x; i < E; i += blockDim.x) dst[i] = src[i];
}

// ---------------- final hinge loss + accuracy -------------------------------
__device__ __forceinline__ float blockReduceSum(float v, float* sbuf)
{
    const int tid = threadIdx.x;
    sbuf[tid] = v;
    __syncthreads();
    for (int s = 128; s > 0; s >>= 1) {
        if (tid < s) sbuf[tid] += sbuf[tid + s];
        __syncthreads();
    }
    const float r = sbuf[0];
    __syncthreads();
    return r;
}

__global__ void zero_out(float* out)
{
    if (threadIdx.x < 2) out[threadIdx.x] = 0.f;
}

__global__ void final_reduce(const float* __restrict__ ts,
                             const float* __restrict__ ds,
                             const float* __restrict__ lp,
                             float* __restrict__ out)
{
    __shared__ float sbuf[256];
    const int j = blockIdx.x;
    float S = 0.f, tp = 0.f;
    float dp[4] = {0.f, 0.f, 0.f, 0.f};
    for (int k = threadIdx.x; k < B_; k += 256) {
        const float t = ts[(size_t)j * B_ + k];
        const float l = lp[k];
        float hsum = 0.f;
#pragma unroll
        for (int d = 0; d < D_; ++d) {
            const float dv = ds[((size_t)d * B_ + j) * B_ + k];
            hsum += fmaxf(0.f, 1.f - t + dv);
            dp[d] += expf(dv);
        }
        S += hsum * l;
        tp += expf(t);
    }
    S  = blockReduceSum(S, sbuf);
    tp = blockReduceSum(tp, sbuf);
    float dpr[4];
#pragma unroll
    for (int d = 0; d < D_; ++d) dpr[d] = blockReduceSum(dp[d], sbuf);
    if (threadIdx.x == 0) {
        atomicAdd(&out[0], -S * (1.f / ((float)B_ * (float)B_)));
        const int win = (tp >= dpr[0]) && (tp >= dpr[1]) &&
                        (tp >= dpr[2]) && (tp >= dpr[3]);
        atomicAdd(&out[1], win ? (1.f / (float)B_) : 0.f);
    }
}

// ---------------- host side --------------------------------------------------
static inline void gemm(const float* A, const float* Bm, float* C,
                        const float* bias, int M, int N, int K, int accum)
{
    dim3 grid((N + 127) / 128, M / 128);
    sgemm_nt<<<grid, 256>>>(A, Bm, C, bias, M, N, K, accum);
}

extern "C" void kernel_launch(void* const* d_in, const int* in_sizes, int n_in,
                              void* d_out, int out_size)
{
    (void)in_sizes; (void)n_in; (void)out_size;

    const float* target   = (const float*)d_in[0];
    const float* distract = (const float*)d_in[1];
    const int*   start    = (const int*)d_in[2];
    /* d_in[3] = max_sentence_length (compile-time L_=20) */
    const float* emb_s  = (const float*)d_in[4];
    const float* Wih_s  = (const float*)d_in[5];
    const float* Whh_s  = (const float*)d_in[6];
    const float* bih_s  = (const float*)d_in[7];
    const float* bhh_s  = (const float*)d_in[8];
    const float* affsW  = (const float*)d_in[9];
    const float* affsb  = (const float*)d_in[10];
    const float* probsW = (const float*)d_in[11];
    const float* probsb = (const float*)d_in[12];
    const float* emb_r  = (const float*)d_in[13];
    const float* Wih_r  = (const float*)d_in[14];
    const float* Whh_r  = (const float*)d_in[15];
    const float* bih_r  = (const float*)d_in[16];
    const float* bhh_r  = (const float*)d_in[17];
    const float* affrW  = (const float*)d_in[18];
    const float* affrb  = (const float*)d_in[19];
    float* out = (float*)d_out;

    float *h, *c, *hr, *cr, *x, *gates, *logits, *r, *ts, *ds, *lp;
    int* msg;
    cudaGetSymbolAddress((void**)&h,      g_h);
    cudaGetSymbolAddress((void**)&c,      g_c);
    cudaGetSymbolAddress((void**)&hr,     g_hr);
    cudaGetSymbolAddress((void**)&cr,     g_cr);
    cudaGetSymbolAddress((void**)&x,      g_x);
    cudaGetSymbolAddress((void**)&gates,  g_gates);
    cudaGetSymbolAddress((void**)&logits, g_logits);
    cudaGetSymbolAddress((void**)&r,      g_r);
    cudaGetSymbolAddress((void**)&ts,     g_ts);
    cudaGetSymbolAddress((void**)&ds,     g_ds);
    cudaGetSymbolAddress((void**)&lp,     g_lp);
    cudaGetSymbolAddress((void**)&msg,    g_msg);

    zero_out<<<1, 32>>>(out);

    // h0 = target @ aff_s_W^T + aff_s_b    [B,H], K=F
    gemm(target, affsW, h, affsb, B_, H_, F_, 0);
    // w0 = emb_s[start_token_idx] broadcast
    gather_emb<<<B_, 128>>>(emb_s, nullptr, start, x, E_);

    // ---- Sender loop ----
    for (int t = 0; t < L_; ++t) {
        gemm(x, Wih_s, gates, bih_s, B_, 4 * H_, E_, 0);
        gemm(h, Whh_s, gates, bhh_s, B_, 4 * H_, H_, 1);
        lstm_update<<<(B_ * H_) / 256, 256>>>(gates, h, c, t == 0);
        gemm(h, probsW, logits, probsb, B_, V_, H_, 0);
        argmax_lse<<<B_, 256>>>(logits, msg + t * B_, lp, t == L_ - 1);
        if (t < L_ - 1)
            gather_emb<<<B_, 128>>>(emb_s, msg + t * B_, nullptr, x, E_);
    }

    // ---- Receiver loop ----
    for (int t = 0; t < L_; ++t) {
        gather_emb<<<B_, 128>>>(emb_r, msg + t * B_, nullptr, x, E_);
        gemm(x, Wih_r, gates, bih_r, B_, 4 * H_, E_, 0);
        gemm(hr, Whh_r, gates, bhh_r, B_, 4 * H_, H_, 1);
        lstm_update<<<(B_ * H_) / 256, 256>>>(gates, hr, cr, t == 0);
    }

    // r = hr @ aff_r_W^T + aff_r_b    [B,F], K=H
    gemm(hr, affrW, r, affrb, B_, F_, H_, 0);

    // ts = target @ r^T  [B,B];  ds[d] = distractors[d] @ r^T  [D,B,B]
    gemm(target,   r, ts, nullptr, B_,      B_, F_, 0);
    gemm(distract, r, ds, nullptr, D_ * B_, B_, F_, 0);

    final_reduce<<<B_, 256>>>(ts, ds, lp, out);
}